// round 1
// baseline (speedup 1.0000x reference)
#include <cuda_runtime.h>
#include <cstdint>

#define NN 2048
#define TT 128
#define FF 64
#define HH 128
#define GG 384   // 3*H
#define EE 32768

// ---------------- scratch (device globals: no allocs allowed) ----------------
__device__ float g_deg[NN];
__device__ float g_dinv[NN];
__device__ float g_xs1[NN*HH];
__device__ float g_acc1[NN*HH];
__device__ float g_h1[NN*HH];
__device__ float g_xs2[NN*HH];
__device__ float g_acc2[NN*HH];
__device__ float g_h2[NN*HH];
__device__ float g_wT[HH*GG];     // w_ih transposed: [k][g]
__device__ float g_gi[NN*GG];     // precomputed input gates (+b_ih)
__device__ float g_hist[NN*HH];   // h after each GRU step
__device__ int   g_stride;        // 1 if edge_index is int32, 2 if int64 words

// ---------------- helpers ----------------
__device__ __forceinline__ unsigned long long ffma2(unsigned long long a,
                                                    unsigned long long b,
                                                    unsigned long long c) {
    asm("fma.rn.f32x2 %0, %1, %2, %0;" : "+l"(c) : "l"(a), "l"(b));
    return c;
}
__device__ __forceinline__ float2 unpack2(unsigned long long v) {
    float2 r; asm("mov.b64 {%0,%1}, %2;" : "=f"(r.x), "=f"(r.y) : "l"(v)); return r;
}

// ---------------- kernels ----------------

// Detect int32 vs int64 edge_index by inspecting high words (values < 2048, so
// int64 storage means every odd 32-bit word is zero).
__global__ void k_detect(const int* __restrict__ ei) {
    int any = 0;
    for (int i = threadIdx.x; i < 1024; i += 32) any |= ei[2*i + 1];
    unsigned b = __ballot_sync(0xFFFFFFFFu, any != 0);
    if (threadIdx.x == 0) g_stride = b ? 1 : 2;
}

__global__ void k_init() {
    int i = blockIdx.x * blockDim.x + threadIdx.x;
    if (i < NN*HH) { g_acc1[i] = 0.f; g_acc2[i] = 0.f; }
    if (i < NN)    g_deg[i] = 1.0f;   // self loop
}

__global__ void k_deg(const int* __restrict__ ei) {
    int e = blockIdx.x * blockDim.x + threadIdx.x;
    if (e < EE) {
        int s = g_stride;
        int d = ei[(EE + e) * s];
        atomicAdd(&g_deg[d], 1.0f);
    }
}

__global__ void k_dinv() {
    int n = blockIdx.x * blockDim.x + threadIdx.x;
    if (n < NN) g_dinv[n] = rsqrtf(g_deg[n]);
}

// xs1[n,:] = dinv[n] * (x[n,127,:] @ W1)
__global__ void k_xs1(const float* __restrict__ x, const float* __restrict__ W1) {
    __shared__ float xr[FF];
    int n = blockIdx.x, t = threadIdx.x;
    if (t < FF) xr[t] = x[n*(TT*FF) + 127*FF + t];
    __syncthreads();
    float a = 0.f;
    #pragma unroll
    for (int k = 0; k < FF; k++) a = fmaf(xr[k], W1[k*HH + t], a);
    g_xs1[n*HH + t] = a * g_dinv[n];
}

__global__ void k_scat1(const int* __restrict__ ei) {
    int t = threadIdx.x;
    int e = blockIdx.x * 4 + (t >> 7);
    int j = t & 127;
    int s = g_stride;
    int sr = ei[e * s], d = ei[(EE + e) * s];
    atomicAdd(&g_acc1[d*HH + j], g_xs1[sr*HH + j]);
}

__global__ void k_fin1(const float* __restrict__ b1) {
    int i = blockIdx.x * blockDim.x + threadIdx.x;
    if (i < NN*HH) {
        int n = i >> 7;
        g_h1[i] = g_dinv[n] * (g_acc1[i] + g_xs1[i]) + b1[i & 127];
    }
}

__global__ void k_xs2(const float* __restrict__ W2) {
    __shared__ float hr[HH];
    int n = blockIdx.x, t = threadIdx.x;
    hr[t] = g_h1[n*HH + t];
    __syncthreads();
    float a = 0.f;
    #pragma unroll
    for (int k = 0; k < HH; k++) a = fmaf(hr[k], W2[k*HH + t], a);
    g_xs2[n*HH + t] = a * g_dinv[n];
}

__global__ void k_scat2(const int* __restrict__ ei) {
    int t = threadIdx.x;
    int e = blockIdx.x * 4 + (t >> 7);
    int j = t & 127;
    int s = g_stride;
    int sr = ei[e * s], d = ei[(EE + e) * s];
    atomicAdd(&g_acc2[d*HH + j], g_xs2[sr*HH + j]);
}

__global__ void k_fin2(const float* __restrict__ b2) {
    int i = blockIdx.x * blockDim.x + threadIdx.x;
    if (i < NN*HH) {
        int n = i >> 7;
        g_h2[i] = g_dinv[n] * (g_acc2[i] + g_xs2[i]) + b2[i & 127];
    }
}

__global__ void k_wT(const float* __restrict__ wih) {
    int i = blockIdx.x * blockDim.x + threadIdx.x;
    if (i < GG*HH) { int g = i >> 7, k = i & 127; g_wT[k*GG + g] = wih[i]; }
}

// GI[n,g] = h2[n,:] . w_ih[g,:] + b_ih[g]   (16 rows per block)
__global__ void k_gi(const float* __restrict__ bih) {
    __shared__ float hs[16][HH];
    int g = threadIdx.x;
    int n0 = blockIdx.x * 16;
    for (int i = g; i < 16*HH; i += GG) hs[i >> 7][i & 127] = g_h2[n0*HH + i];
    __syncthreads();
    float acc[16];
    #pragma unroll
    for (int i = 0; i < 16; i++) acc[i] = 0.f;
    for (int k = 0; k < HH; k++) {
        float w = g_wT[k*GG + g];
        #pragma unroll
        for (int i = 0; i < 16; i++) acc[i] = fmaf(hs[i][k], w, acc[i]);
    }
    float b = bih[g];
    #pragma unroll
    for (int i = 0; i < 16; i++) g_gi[(n0 + i)*GG + g] = acc[i] + b;
}

// Sequential GRU over n=0..2047 (the scan axis), hidden = one [128] vector.
// 512 threads: thread (j, kc) = (tid>>2, tid&3) accumulates rows j, j+128,
// j+256 of w_hh over k in [kc*32, kc*32+32). Weights in registers (f32x2).
// h lives in shared, padded to 17-float2 chunks -> conflict-free broadcast.
__global__ __launch_bounds__(512, 1) void k_gru(const float* __restrict__ whh,
                                                const float* __restrict__ bhh) {
    __shared__ __align__(16) float hbuf[2][4*34];   // chunk c: floats [c*34, c*34+32)
    __shared__ float gibuf[2][GG];
    int tid = threadIdx.x;
    int j = tid >> 2, kc = tid & 3;

    unsigned long long wr[16], wz[16], wn[16];
    const unsigned long long* r0 = (const unsigned long long*)(whh + (size_t)j*HH)        + kc*16;
    const unsigned long long* r1 = (const unsigned long long*)(whh + (size_t)(j+HH)*HH)   + kc*16;
    const unsigned long long* r2 = (const unsigned long long*)(whh + (size_t)(j+2*HH)*HH) + kc*16;
    #pragma unroll
    for (int t = 0; t < 16; t++) { wr[t] = r0[t]; wz[t] = r1[t]; wn[t] = r2[t]; }

    float bh_r = 0.f, bh_z = 0.f, bh_n = 0.f;
    if (kc == 0) { bh_r = bhh[j]; bh_z = bhh[HH + j]; bh_n = bhh[2*HH + j]; }
    float hj = 0.f;

    if (tid < 4*34) { hbuf[0][tid] = 0.f; hbuf[1][tid] = 0.f; }
    if (tid < GG)   gibuf[0][tid] = g_gi[tid];
    __syncthreads();

    int p = 0;
    const int hoff = kc * 17;   // float2 offset of this thread's k-chunk
    for (int n = 0; n < NN; n++) {
        // prefetch next step's input gates (independent of h -> latency hidden)
        float ginext = 0.f;
        if (tid < GG && n < NN - 1) ginext = g_gi[(size_t)(n + 1)*GG + tid];

        const unsigned long long* hp = (const unsigned long long*)(&hbuf[p][0]) + hoff;
        unsigned long long ar = 0ull, az = 0ull, an_ = 0ull;
        #pragma unroll
        for (int t = 0; t < 16; t++) {
            unsigned long long hv = hp[t];
            ar  = ffma2(wr[t], hv, ar);
            az  = ffma2(wz[t], hv, az);
            an_ = ffma2(wn[t], hv, an_);
        }
        float2 fr = unpack2(ar), fz = unpack2(az), fn = unpack2(an_);
        float sr = fr.x + fr.y, sz = fz.x + fz.y, sn = fn.x + fn.y;
        sr += __shfl_xor_sync(0xFFFFFFFFu, sr, 1);
        sz += __shfl_xor_sync(0xFFFFFFFFu, sz, 1);
        sn += __shfl_xor_sync(0xFFFFFFFFu, sn, 1);
        sr += __shfl_xor_sync(0xFFFFFFFFu, sr, 2);
        sz += __shfl_xor_sync(0xFFFFFFFFu, sz, 2);
        sn += __shfl_xor_sync(0xFFFFFFFFu, sn, 2);

        if (kc == 0) {
            float gir = gibuf[p][j], giz = gibuf[p][HH + j], gin = gibuf[p][2*HH + j];
            float r  = 1.f / (1.f + __expf(-(gir + sr + bh_r)));
            float z  = 1.f / (1.f + __expf(-(giz + sz + bh_z)));
            float nn = tanhf(gin + r * (sn + bh_n));
            hj = (1.f - z) * nn + z * hj;
            hbuf[p ^ 1][(j >> 5) * 34 + (j & 31)] = hj;
            g_hist[(size_t)n*HH + j] = hj;
        }
        if (tid < GG) gibuf[p ^ 1][tid] = ginext;
        __syncthreads();
        p ^= 1;
    }
}

// out[n] = hist[n,:] . fc_w + fc_b  (one warp per n)
__global__ void k_out(const float* __restrict__ fcw, const float* __restrict__ fcb,
                      float* __restrict__ out) {
    int w = threadIdx.x >> 5, lane = threadIdx.x & 31;
    int n = blockIdx.x * 8 + w;
    const float4* hp = (const float4*)(g_hist + (size_t)n*HH);
    const float4* wp = (const float4*)fcw;
    float4 h = hp[lane], ww = wp[lane];
    float s = h.x*ww.x + h.y*ww.y + h.z*ww.z + h.w*ww.w;
    s += __shfl_xor_sync(0xFFFFFFFFu, s, 16);
    s += __shfl_xor_sync(0xFFFFFFFFu, s, 8);
    s += __shfl_xor_sync(0xFFFFFFFFu, s, 4);
    s += __shfl_xor_sync(0xFFFFFFFFu, s, 2);
    s += __shfl_xor_sync(0xFFFFFFFFu, s, 1);
    if (lane == 0) out[n] = s + fcb[0];
}

// ---------------- launch ----------------
extern "C" void kernel_launch(void* const* d_in, const int* in_sizes, int n_in,
                              void* d_out, int out_size) {
    const float* x   = (const float*)d_in[0];
    const int*   ei  = (const int*)  d_in[1];
    const float* W1  = (const float*)d_in[2];
    const float* b1  = (const float*)d_in[3];
    const float* W2  = (const float*)d_in[4];
    const float* b2  = (const float*)d_in[5];
    const float* wih = (const float*)d_in[6];
    const float* whh = (const float*)d_in[7];
    const float* bih = (const float*)d_in[8];
    const float* bhh = (const float*)d_in[9];
    const float* fcw = (const float*)d_in[10];
    const float* fcb = (const float*)d_in[11];
    float* out = (float*)d_out;

    k_detect<<<1, 32>>>(ei);
    k_init<<<(NN*HH + 255)/256, 256>>>();
    k_deg<<<EE/256, 256>>>(ei);
    k_dinv<<<(NN + 255)/256, 256>>>();
    k_xs1<<<NN, HH>>>(x, W1);
    k_scat1<<<EE/4, 512>>>(ei);
    k_fin1<<<NN*HH/256, 256>>>(b1);
    k_xs2<<<NN, HH>>>(W2);
    k_scat2<<<EE/4, 512>>>(ei);
    k_fin2<<<NN*HH/256, 256>>>(b2);
    k_wT<<<GG*HH/256, 256>>>(wih);
    k_gi<<<NN/16, GG>>>(bih);
    k_gru<<<1, 512>>>(whh, bhh);
    k_out<<<NN/8, 256>>>(fcw, fcb, out);
}